// round 8
// baseline (speedup 1.0000x reference)
#include <cuda_runtime.h>
#include <cuda_fp16.h>
#include <math.h>
#include <stdint.h>

// ---------------------------------------------------------------------------
// Scratch (static device arrays; no allocation allowed).
// ---------------------------------------------------------------------------
__device__ __half g_x16[32u * 512u * 512u];    // x  as f16           [B][T][D]
__device__ __half g_h16[32u * 512u * 1024u];   // h  as f16           [B][T][MID]
__device__ __half g_w1t[64u * 1024u * 512u];   // w1 f16, transposed  [S][N=MID][K=D]
__device__ __half g_w2t[64u * 512u * 1024u];   // w2 f16, transposed  [S][N=O][K=MID]

// ---------------------------------------------------------------------------
// helpers
// ---------------------------------------------------------------------------
__device__ __forceinline__ uint32_t smem_u32(const void* p) {
    uint32_t a;
    asm("{ .reg .u64 t; cvta.to.shared.u64 t, %1; cvt.u32.u64 %0, t; }"
        : "=r"(a) : "l"(p));
    return a;
}

__device__ __forceinline__ void cp_async16(uint32_t saddr, const void* gptr) {
    asm volatile("cp.async.cg.shared.global [%0], [%1], 16;"
                 :: "r"(saddr), "l"(gptr) : "memory");
}
__device__ __forceinline__ void cp_commit() {
    asm volatile("cp.async.commit_group;" ::: "memory");
}
template <int N>
__device__ __forceinline__ void cp_wait() {
    asm volatile("cp.async.wait_group %0;" :: "n"(N) : "memory");
}

__device__ __forceinline__ void mma_f16(float c[4], const uint32_t a[4],
                                        uint32_t b0, uint32_t b1) {
    asm volatile(
        "mma.sync.aligned.m16n8k16.row.col.f32.f16.f16.f32 "
        "{%0,%1,%2,%3}, {%4,%5,%6,%7}, {%8,%9}, {%0,%1,%2,%3};"
        : "+f"(c[0]), "+f"(c[1]), "+f"(c[2]), "+f"(c[3])
        : "r"(a[0]), "r"(a[1]), "r"(a[2]), "r"(a[3]), "r"(b0), "r"(b1));
}

// sid dtype sniff (int32 vs int64), proven in rounds 4-7.
__device__ __forceinline__ int load_sid(const int* __restrict__ raw, int b) {
    bool is64 = true;
    #pragma unroll
    for (int i = 0; i < 16; i++)
        if (raw[2 * i + 1] != 0) { is64 = false; break; }
    int s = is64 ? raw[2 * b] : raw[b];
    if (s < 0) s = 0;
    if (s > 63) s = 63;
    return s;
}

// ---------------------------------------------------------------------------
// Conversion kernels
// ---------------------------------------------------------------------------
__global__ void convert_x_kernel(const float4* __restrict__ in,
                                 uint2* __restrict__ out, int n4) {
    for (int i = blockIdx.x * blockDim.x + threadIdx.x; i < n4;
         i += gridDim.x * blockDim.x) {
        float4 v = in[i];
        __half2 lo = __floats2half2_rn(v.x, v.y);
        __half2 hi = __floats2half2_rn(v.z, v.w);
        uint2 u;
        u.x = *reinterpret_cast<uint32_t*>(&lo);
        u.y = *reinterpret_cast<uint32_t*>(&hi);
        out[i] = u;
    }
}

// w [S][K][N] f32 -> wt [S][N][K] f16, used subjects only. 32x32 smem transpose.
__global__ void convert_w_t_kernel(const float* __restrict__ w,
                                   __half* __restrict__ wt,
                                   const int* __restrict__ sid_raw,
                                   int K, int N) {
    const int s = blockIdx.z;
    {
        bool is64 = true;
        #pragma unroll
        for (int i = 0; i < 16; i++)
            if (sid_raw[2 * i + 1] != 0) { is64 = false; break; }
        bool used = false;
        #pragma unroll
        for (int b = 0; b < 32; b++) {
            int v = is64 ? sid_raw[2 * b] : sid_raw[b];
            if (v == s) used = true;
        }
        if (!used) return;
    }
    __shared__ float tile[32][33];
    const int k0 = blockIdx.y * 32, n0 = blockIdx.x * 32;
    const int tx = threadIdx.x, ty = threadIdx.y;
    const float* wp = w + (size_t)s * K * N;
    __half* wtp = wt + (size_t)s * N * K;
    #pragma unroll
    for (int i = ty; i < 32; i += 8)
        tile[i][tx] = wp[(size_t)(k0 + i) * N + n0 + tx];
    __syncthreads();
    #pragma unroll
    for (int i = ty; i < 32; i += 8)
        wtp[(size_t)(n0 + i) * K + k0 + tx] = __float2half_rn(tile[tx][i]);
}

// ---------------------------------------------------------------------------
// fp16 mma.sync GEMM, cp.async 4-stage pipeline.
//   C[b] = act( A[b] @ Wt[sid[b]]^T ) (+ bias[sid[b]])
//   A:  [B, M, K] f16 row-major (K contiguous)
//   Wt: [S, N, K] f16 row-major (K contiguous)
//   CTA tile 128x128, BK=16, 128 threads (4 warps 2x2, warp 64x64).
//   SMEM: per stage, A: 128 rows x 48B (16 f16 + pad), B same. Fragment LDS
//   bank = (12*row + t4) mod 32 -> conflict-free.
// ---------------------------------------------------------------------------
#define NSTAGE 4
static constexpr int ROW_B = 48;                  // smem row stride (bytes)
static constexpr int HALF_STG = 128 * ROW_B;      // 6144 B (A or B half)
static constexpr int STG_B = 2 * HALF_STG;        // 12288 B per stage
static constexpr int SMEM_DYN = NSTAGE * STG_B;   // 49152 B

template <bool DO_GELU, bool DO_BIAS, bool STORE_HALF>
__global__ __launch_bounds__(128, 2)
void subject_hgemm(const __half* __restrict__ A_base,
                   const __half* __restrict__ Wt_base,
                   const int* __restrict__ sid_raw,
                   const float* __restrict__ bias_base,
                   void* __restrict__ C_base,
                   int M, int N, int K)
{
    const int b = blockIdx.z;
    const int s = load_sid(sid_raw, b);
    const __half* A = A_base + (size_t)b * M * K;
    const __half* Wt = Wt_base + (size_t)s * N * K;
    const int m0 = blockIdx.y * 128;
    const int n0 = blockIdx.x * 128;

    extern __shared__ char dsm[];
    const uint32_t smem0 = smem_u32(dsm);

    const int tid = threadIdx.x;
    const int wid = tid >> 5;
    const int lane = tid & 31;
    const int wm = wid >> 1;   // 0..1 -> 64-row slab
    const int wn = wid & 1;    // 0..1 -> 64-col slab
    const int g = lane >> 2;   // 0..7
    const int t4 = lane & 3;   // 0..3

    // cp.async: thread tid owns smem row tid (A: m-row, B: n-row), 2x16B each.
    const __half* Ag = A + (size_t)(m0 + tid) * K;
    const __half* Bg = Wt + (size_t)(n0 + tid) * K;

    const int NC = K / 16;

    auto issue_stage = [&](int c) {
        const uint32_t base = smem0 + (uint32_t)((c % NSTAGE) * STG_B);
        const int k0 = c * 16;
        cp_async16(base + (uint32_t)tid * ROW_B,                Ag + k0);
        cp_async16(base + (uint32_t)tid * ROW_B + 16,           Ag + k0 + 8);
        cp_async16(base + HALF_STG + (uint32_t)tid * ROW_B,     Bg + k0);
        cp_async16(base + HALF_STG + (uint32_t)tid * ROW_B + 16, Bg + k0 + 8);
    };

    float acc[4][8][4];
    #pragma unroll
    for (int i = 0; i < 4; i++)
        #pragma unroll
        for (int j = 0; j < 8; j++)
            #pragma unroll
            for (int q = 0; q < 4; q++)
                acc[i][j][q] = 0.0f;

    #pragma unroll
    for (int c = 0; c < NSTAGE - 1; c++) {
        issue_stage(c);
        cp_commit();
    }

    #pragma unroll 1
    for (int c = 0; c < NC; c++) {
        cp_wait<NSTAGE - 2>();
        __syncthreads();

        if (c + NSTAGE - 1 < NC) issue_stage(c + NSTAGE - 1);
        cp_commit();

        const char* sb = dsm + (size_t)(c % NSTAGE) * STG_B;

        uint32_t af[4][4];
        #pragma unroll
        for (int fm = 0; fm < 4; fm++) {
            const int mr = wm * 64 + fm * 16 + g;
            const char* ap = sb + mr * ROW_B + t4 * 4;
            af[fm][0] = *reinterpret_cast<const uint32_t*>(ap);
            af[fm][1] = *reinterpret_cast<const uint32_t*>(ap + 8 * ROW_B);
            af[fm][2] = *reinterpret_cast<const uint32_t*>(ap + 16);
            af[fm][3] = *reinterpret_cast<const uint32_t*>(ap + 8 * ROW_B + 16);
        }
        uint32_t bf[8][2];
        #pragma unroll
        for (int fn = 0; fn < 8; fn++) {
            const int nr = wn * 64 + fn * 8 + g;
            const char* bp = sb + HALF_STG + nr * ROW_B + t4 * 4;
            bf[fn][0] = *reinterpret_cast<const uint32_t*>(bp);
            bf[fn][1] = *reinterpret_cast<const uint32_t*>(bp + 16);
        }
        #pragma unroll
        for (int fm = 0; fm < 4; fm++)
            #pragma unroll
            for (int fn = 0; fn < 8; fn++)
                mma_f16(acc[fm][fn], af[fm], bf[fn][0], bf[fn][1]);
    }

    // ---- epilogue ----
    const float* brow = DO_BIAS ? (bias_base + (size_t)s * N + n0) : nullptr;

    #pragma unroll
    for (int fm = 0; fm < 4; fm++) {
        const int r0 = m0 + wm * 64 + fm * 16 + g;
        #pragma unroll
        for (int fn = 0; fn < 8; fn++) {
            const int col = wn * 64 + fn * 8 + t4 * 2;
            #pragma unroll
            for (int h2 = 0; h2 < 2; h2++) {
                const int row = r0 + 8 * h2;
                float v0 = acc[fm][fn][2 * h2 + 0];
                float v1 = acc[fm][fn][2 * h2 + 1];
                if (DO_BIAS) {
                    v0 += brow[col];
                    v1 += brow[col + 1];
                }
                if (DO_GELU) {
                    v0 = 0.5f * v0 * (1.0f + erff(v0 * 0.70710678118654752f));
                    v1 = 0.5f * v1 * (1.0f + erff(v1 * 0.70710678118654752f));
                }
                if (STORE_HALF) {
                    __half2 hv = __floats2half2_rn(v0, v1);
                    *reinterpret_cast<__half2*>(
                        (__half*)C_base + (size_t)b * M * N +
                        (size_t)row * N + n0 + col) = hv;
                } else {
                    *reinterpret_cast<float2*>(
                        (float*)C_base + (size_t)b * M * N +
                        (size_t)row * N + n0 + col) = make_float2(v0, v1);
                }
            }
        }
    }
}

// ---------------------------------------------------------------------------
extern "C" void kernel_launch(void* const* d_in, const int* in_sizes, int n_in,
                              void* d_out, int out_size) {
    const float* x = (const float*)d_in[0];     // [32, 512, 512]
    const int* sid_raw = (const int*)d_in[1];   // [32] int32 or int64 (sniffed)
    const float* w1 = (const float*)d_in[2];    // [64, 512, 1024]
    const float* w2 = (const float*)d_in[3];    // [64, 1024, 512]
    const float* bias = (const float*)d_in[4];  // [64, 512]
    float* out = (float*)d_out;                 // [32, 512, 512]

    const int B = 32, T = 512, D = 512, MID = 1024, O = 512;
    (void)in_sizes; (void)n_in; (void)out_size;

    __half *x16, *h16, *w1t, *w2t;
    cudaGetSymbolAddress((void**)&x16, g_x16);
    cudaGetSymbolAddress((void**)&h16, g_h16);
    cudaGetSymbolAddress((void**)&w1t, g_w1t);
    cudaGetSymbolAddress((void**)&w2t, g_w2t);

    (void)cudaFuncSetAttribute(
        (const void*)subject_hgemm<true, false, true>,
        cudaFuncAttributeMaxDynamicSharedMemorySize, SMEM_DYN);
    (void)cudaFuncSetAttribute(
        (const void*)subject_hgemm<false, true, false>,
        cudaFuncAttributeMaxDynamicSharedMemorySize, SMEM_DYN);

    // 1) x -> f16
    {
        const int n4 = (B * T * D) / 4;
        convert_x_kernel<<<4096, 256>>>((const float4*)x, (uint2*)x16, n4);
    }
    // 2) w1, w2 -> f16 transposed [S][N][K], used subjects only
    {
        dim3 tb(32, 8);
        convert_w_t_kernel<<<dim3(MID / 32, D / 32, 64), tb>>>(w1, w1t, sid_raw, D, MID);
        convert_w_t_kernel<<<dim3(O / 32, MID / 32, 64), tb>>>(w2, w2t, sid_raw, MID, O);
    }
    // 3) GEMM1 + GELU -> h16:  (M=512, N=1024, K=512)
    {
        dim3 grid(MID / 128, T / 128, B);
        subject_hgemm<true, false, true><<<grid, 128, SMEM_DYN>>>(
            x16, w1t, sid_raw, nullptr, (void*)h16, T, MID, D);
    }
    // 4) GEMM2 + bias -> out f32:  (M=512, N=512, K=1024)
    {
        dim3 grid(O / 128, T / 128, B);
        subject_hgemm<false, true, false><<<grid, 128, SMEM_DYN>>>(
            h16, w2t, sid_raw, bias, (void*)out, T, O, MID);
    }
}

// round 9
// speedup vs baseline: 1.2303x; 1.2303x over previous
#include <cuda_runtime.h>
#include <cuda_fp16.h>
#include <math.h>
#include <stdint.h>

// ---------------------------------------------------------------------------
// Scratch (static device arrays; no allocation allowed).
// ---------------------------------------------------------------------------
__device__ __half g_x16[32u * 512u * 512u];    // x  as f16           [B][T][D]
__device__ __half g_h16[32u * 512u * 1024u];   // h  as f16           [B][T][MID]
__device__ __half g_w1t[64u * 1024u * 512u];   // w1 f16, transposed  [S][N=MID][K=D]
__device__ __half g_w2t[64u * 512u * 1024u];   // w2 f16, transposed  [S][N=O][K=MID]

// ---------------------------------------------------------------------------
// helpers
// ---------------------------------------------------------------------------
__device__ __forceinline__ uint32_t smem_u32(const void* p) {
    uint32_t a;
    asm("{ .reg .u64 t; cvta.to.shared.u64 t, %1; cvt.u32.u64 %0, t; }"
        : "=r"(a) : "l"(p));
    return a;
}

__device__ __forceinline__ void cp_async16(uint32_t saddr, const void* gptr) {
    asm volatile("cp.async.cg.shared.global [%0], [%1], 16;"
                 :: "r"(saddr), "l"(gptr) : "memory");
}
__device__ __forceinline__ void cp_commit() {
    asm volatile("cp.async.commit_group;" ::: "memory");
}
template <int N>
__device__ __forceinline__ void cp_wait() {
    asm volatile("cp.async.wait_group %0;" :: "n"(N) : "memory");
}

__device__ __forceinline__ void ldsm_x4(uint32_t r[4], uint32_t addr) {
    asm volatile("ldmatrix.sync.aligned.m8n8.x4.shared.b16 {%0,%1,%2,%3}, [%4];"
                 : "=r"(r[0]), "=r"(r[1]), "=r"(r[2]), "=r"(r[3])
                 : "r"(addr));
}

__device__ __forceinline__ void mma_f16(float c[4], const uint32_t a[4],
                                        uint32_t b0, uint32_t b1) {
    asm volatile(
        "mma.sync.aligned.m16n8k16.row.col.f32.f16.f16.f32 "
        "{%0,%1,%2,%3}, {%4,%5,%6,%7}, {%8,%9}, {%0,%1,%2,%3};"
        : "+f"(c[0]), "+f"(c[1]), "+f"(c[2]), "+f"(c[3])
        : "r"(a[0]), "r"(a[1]), "r"(a[2]), "r"(a[3]), "r"(b0), "r"(b1));
}

// sid dtype sniff (int32 vs int64), proven in rounds 4-8.
__device__ __forceinline__ int load_sid(const int* __restrict__ raw, int b) {
    bool is64 = true;
    #pragma unroll
    for (int i = 0; i < 16; i++)
        if (raw[2 * i + 1] != 0) { is64 = false; break; }
    int s = is64 ? raw[2 * b] : raw[b];
    if (s < 0) s = 0;
    if (s > 63) s = 63;
    return s;
}

// ---------------------------------------------------------------------------
// Conversion kernels
// ---------------------------------------------------------------------------
__global__ void convert_x_kernel(const float4* __restrict__ in,
                                 uint2* __restrict__ out, int n4) {
    for (int i = blockIdx.x * blockDim.x + threadIdx.x; i < n4;
         i += gridDim.x * blockDim.x) {
        float4 v = in[i];
        __half2 lo = __floats2half2_rn(v.x, v.y);
        __half2 hi = __floats2half2_rn(v.z, v.w);
        uint2 u;
        u.x = *reinterpret_cast<uint32_t*>(&lo);
        u.y = *reinterpret_cast<uint32_t*>(&hi);
        out[i] = u;
    }
}

// w [S][K][N] f32 -> wt [S][N][K] f16, used subjects only. 32x32 smem transpose.
__global__ void convert_w_t_kernel(const float* __restrict__ w,
                                   __half* __restrict__ wt,
                                   const int* __restrict__ sid_raw,
                                   int K, int N) {
    const int s = blockIdx.z;
    {
        bool is64 = true;
        #pragma unroll
        for (int i = 0; i < 16; i++)
            if (sid_raw[2 * i + 1] != 0) { is64 = false; break; }
        bool used = false;
        #pragma unroll
        for (int b = 0; b < 32; b++) {
            int v = is64 ? sid_raw[2 * b] : sid_raw[b];
            if (v == s) used = true;
        }
        if (!used) return;
    }
    __shared__ float tile[32][33];
    const int k0 = blockIdx.y * 32, n0 = blockIdx.x * 32;
    const int tx = threadIdx.x, ty = threadIdx.y;
    const float* wp = w + (size_t)s * K * N;
    __half* wtp = wt + (size_t)s * N * K;
    #pragma unroll
    for (int i = ty; i < 32; i += 8)
        tile[i][tx] = wp[(size_t)(k0 + i) * N + n0 + tx];
    __syncthreads();
    #pragma unroll
    for (int i = ty; i < 32; i += 8)
        wtp[(size_t)(n0 + i) * K + k0 + tx] = __float2half_rn(tile[tx][i]);
}

// ---------------------------------------------------------------------------
// fp16 mma.sync GEMM, cp.async 4-stage pipeline, ldmatrix fragments.
//   C[b] = act( A[b] @ Wt[sid[b]]^T ) (+ bias[sid[b]])
//   A:  [B, M, K] f16 row-major (K contiguous)
//   Wt: [S, N, K] f16 row-major (K contiguous)
//   CTA tile 128x128, BK=16, 256 threads (8 warps 4(m)x2(n), warp 32x64).
//   SMEM rows: 16 f16 = 32B data + 16B pad = 48B stride -> LDSM conflict-free.
// ---------------------------------------------------------------------------
#define NSTAGE 4
static constexpr int ROW_B = 48;                  // smem row stride (bytes)
static constexpr int HALF_STG = 128 * ROW_B;      // 6144 B (A or B half)
static constexpr int STG_B = 2 * HALF_STG;        // 12288 B per stage
static constexpr int SMEM_DYN = NSTAGE * STG_B;   // 49152 B

template <bool DO_GELU, bool DO_BIAS, bool STORE_HALF>
__global__ __launch_bounds__(256, 2)
void subject_hgemm(const __half* __restrict__ A_base,
                   const __half* __restrict__ Wt_base,
                   const int* __restrict__ sid_raw,
                   const float* __restrict__ bias_base,
                   void* __restrict__ C_base,
                   int M, int N, int K)
{
    const int b = blockIdx.z;
    const int s = load_sid(sid_raw, b);
    const __half* A = A_base + (size_t)b * M * K;
    const __half* Wt = Wt_base + (size_t)s * N * K;
    const int m0 = blockIdx.y * 128;
    const int n0 = blockIdx.x * 128;

    extern __shared__ char dsm[];
    const uint32_t smem0 = smem_u32(dsm);

    const int tid = threadIdx.x;
    const int wid = tid >> 5;
    const int lane = tid & 31;
    const int wm = wid >> 1;   // 0..3 -> 32-row slab
    const int wn = wid & 1;    // 0..1 -> 64-col slab
    const int g = lane >> 2;   // 0..7
    const int t4 = lane & 3;   // 0..3

    // cp.async: thread -> (row tid>>1, 16B half tid&1) for both A and B halves.
    const int cR = tid >> 1, cH = tid & 1;
    const __half* Ag = A + (size_t)(m0 + cR) * K + cH * 8;
    const __half* Bg = Wt + (size_t)(n0 + cR) * K + cH * 8;
    const uint32_t cpOffA = (uint32_t)(cR * ROW_B + cH * 16);
    const uint32_t cpOffB = HALF_STG + cpOffA;

    // ldmatrix lane addresses (within a stage):
    //  A .x4 loads one m16k16 fragment: lanes 0-15 -> rows base+0..15 (byte 0),
    //  lanes 16-31 -> rows base+0..15 (byte 16).
    const uint32_t aAddr0 = smem0
        + (uint32_t)((wm * 32 + (lane & 15)) * ROW_B + (lane >> 4) * 16);
    //  B .x4 loads two n8k16 fragments (rows base..+7 and base+8..+15):
    //  lanes 0-7: row base+(l&7), byte 0;   lanes 8-15: row base+(l&7), byte 16;
    //  lanes 16-23: row base+8+(l&7), b 0;  lanes 24-31: row base+8+(l&7), b 16.
    const uint32_t bAddr0 = smem0 + HALF_STG
        + (uint32_t)((wn * 64 + (lane & 7) + ((lane >> 4) << 3)) * ROW_B
                     + ((lane >> 3) & 1) * 16);

    const int NC = K / 16;

    auto issue_stage = [&](int c) {
        const uint32_t base = (uint32_t)((c % NSTAGE) * STG_B);
        const int k0 = c * 16;
        cp_async16(smem0 + base + cpOffA, Ag + k0);
        cp_async16(smem0 + base + cpOffB, Bg + k0);
    };

    float acc[2][8][4];
    #pragma unroll
    for (int i = 0; i < 2; i++)
        #pragma unroll
        for (int j = 0; j < 8; j++)
            #pragma unroll
            for (int q = 0; q < 4; q++)
                acc[i][j][q] = 0.0f;

    #pragma unroll
    for (int c = 0; c < NSTAGE - 1; c++) {
        issue_stage(c);
        cp_commit();
    }

    #pragma unroll 1
    for (int c = 0; c < NC; c++) {
        cp_wait<NSTAGE - 2>();
        __syncthreads();

        if (c + NSTAGE - 1 < NC) issue_stage(c + NSTAGE - 1);
        cp_commit();

        const uint32_t soff = (uint32_t)((c % NSTAGE) * STG_B);

        uint32_t af[2][4];
        ldsm_x4(af[0], aAddr0 + soff);
        ldsm_x4(af[1], aAddr0 + soff + 16 * ROW_B);

        uint32_t bf[4][4];  // bf[j] = fragments 2j (r0,r1) and 2j+1 (r2,r3)
        #pragma unroll
        for (int j = 0; j < 4; j++)
            ldsm_x4(bf[j], bAddr0 + soff + (uint32_t)(j * 16 * ROW_B));

        #pragma unroll
        for (int fm = 0; fm < 2; fm++)
            #pragma unroll
            for (int j = 0; j < 4; j++) {
                mma_f16(acc[fm][2 * j + 0], af[fm], bf[j][0], bf[j][1]);
                mma_f16(acc[fm][2 * j + 1], af[fm], bf[j][2], bf[j][3]);
            }
    }

    // ---- epilogue ----
    const float* brow = DO_BIAS ? (bias_base + (size_t)s * N + n0) : nullptr;

    #pragma unroll
    for (int fm = 0; fm < 2; fm++) {
        const int r0 = m0 + wm * 32 + fm * 16 + g;
        #pragma unroll
        for (int fn = 0; fn < 8; fn++) {
            const int col = wn * 64 + fn * 8 + t4 * 2;
            #pragma unroll
            for (int h2 = 0; h2 < 2; h2++) {
                const int row = r0 + 8 * h2;
                float v0 = acc[fm][fn][2 * h2 + 0];
                float v1 = acc[fm][fn][2 * h2 + 1];
                if (DO_BIAS) {
                    v0 += brow[col];
                    v1 += brow[col + 1];
                }
                if (DO_GELU) {
                    v0 = 0.5f * v0 * (1.0f + erff(v0 * 0.70710678118654752f));
                    v1 = 0.5f * v1 * (1.0f + erff(v1 * 0.70710678118654752f));
                }
                if (STORE_HALF) {
                    __half2 hv = __floats2half2_rn(v0, v1);
                    *reinterpret_cast<__half2*>(
                        (__half*)C_base + (size_t)b * M * N +
                        (size_t)row * N + n0 + col) = hv;
                } else {
                    *reinterpret_cast<float2*>(
                        (float*)C_base + (size_t)b * M * N +
                        (size_t)row * N + n0 + col) = make_float2(v0, v1);
                }
            }
        }
    }
}

// ---------------------------------------------------------------------------
extern "C" void kernel_launch(void* const* d_in, const int* in_sizes, int n_in,
                              void* d_out, int out_size) {
    const float* x = (const float*)d_in[0];     // [32, 512, 512]
    const int* sid_raw = (const int*)d_in[1];   // [32] int32 or int64 (sniffed)
    const float* w1 = (const float*)d_in[2];    // [64, 512, 1024]
    const float* w2 = (const float*)d_in[3];    // [64, 1024, 512]
    const float* bias = (const float*)d_in[4];  // [64, 512]
    float* out = (float*)d_out;                 // [32, 512, 512]

    const int B = 32, T = 512, D = 512, MID = 1024, O = 512;
    (void)in_sizes; (void)n_in; (void)out_size;

    __half *x16, *h16, *w1t, *w2t;
    cudaGetSymbolAddress((void**)&x16, g_x16);
    cudaGetSymbolAddress((void**)&h16, g_h16);
    cudaGetSymbolAddress((void**)&w1t, g_w1t);
    cudaGetSymbolAddress((void**)&w2t, g_w2t);

    (void)cudaFuncSetAttribute(
        (const void*)subject_hgemm<true, false, true>,
        cudaFuncAttributeMaxDynamicSharedMemorySize, SMEM_DYN);
    (void)cudaFuncSetAttribute(
        (const void*)subject_hgemm<false, true, false>,
        cudaFuncAttributeMaxDynamicSharedMemorySize, SMEM_DYN);

    // 1) x -> f16
    {
        const int n4 = (B * T * D) / 4;
        convert_x_kernel<<<4096, 256>>>((const float4*)x, (uint2*)x16, n4);
    }
    // 2) w1, w2 -> f16 transposed [S][N][K], used subjects only
    {
        dim3 tb(32, 8);
        convert_w_t_kernel<<<dim3(MID / 32, D / 32, 64), tb>>>(w1, w1t, sid_raw, D, MID);
        convert_w_t_kernel<<<dim3(O / 32, MID / 32, 64), tb>>>(w2, w2t, sid_raw, MID, O);
    }
    // 3) GEMM1 + GELU -> h16:  (M=512, N=1024, K=512)
    {
        dim3 grid(MID / 128, T / 128, B);
        subject_hgemm<true, false, true><<<grid, 256, SMEM_DYN>>>(
            x16, w1t, sid_raw, nullptr, (void*)h16, T, MID, D);
    }
    // 4) GEMM2 + bias -> out f32:  (M=512, N=512, K=1024)
    {
        dim3 grid(O / 128, T / 128, B);
        subject_hgemm<false, true, false><<<grid, 256, SMEM_DYN>>>(
            h16, w2t, sid_raw, bias, (void*)out, T, O, MID);
    }
}